// round 3
// baseline (speedup 1.0000x reference)
#include <cuda_runtime.h>
#include <cuda_bf16.h>

// SparseBoundaryContent: B=16, D=512, N=64.
// Closed form: on masked (i,j): boundary = 0.5*(x[i]+x[j]), content = max(x[i..j]);
// diag = x[i]; else 0. Mask static in (i,j). Output = [boundary | content | mask] f32.

#define NN 64

__device__ __forceinline__ bool is_masked(int i, int off) {
    // off = j - i
    if (off < 0) return false;
    if (off <= 15) return true;                               // offs 0..15, all i
    if (off <= 31) return (off & 1) && ((i & 1) == 0);        // 17,19,..,31; i even
    if (off >= 35) return ((off & 3) == 3) && ((i & 3) == 0); // 35,39,..,63; i%4==0
    return false;
}

__device__ __forceinline__ void stcs4(float4* p, float a, float b, float c, float d) {
    float4 v = make_float4(a, b, c, d);
    __stcs(p, v);
}

__global__ void __launch_bounds__(256)
sbc_kernel(const float* __restrict__ x, float* __restrict__ out,
           int BD, int nMaskB) {
    const int blk = blockIdx.x;
    const int t = threadIdx.x;

    if (blk < BD) {
        __shared__ float st[7][NN];

        // Level 0 = x row.
        if (t < 16) {
            float4 v = reinterpret_cast<const float4*>(x + (size_t)blk * NN)[t];
            st[0][t * 4 + 0] = v.x;
            st[0][t * 4 + 1] = v.y;
            st[0][t * 4 + 2] = v.z;
            st[0][t * 4 + 3] = v.w;
        }
        __syncthreads();

        float4* bptr = reinterpret_cast<float4*>(out) + (size_t)blk * 1024;
        float4* cptr = reinterpret_cast<float4*>(out) + (size_t)BD * 1024 + (size_t)blk * 1024;

        // --- Boundary tile first: needs only st[0]. Gets stores in flight while
        // the max table is still being built. ---
        #pragma unroll
        for (int it = 0; it < 4; ++it) {
            int q  = t + it * 256;
            int i  = q >> 4;
            int j0 = (q & 15) << 2;
            float xi = st[0][i];
            float bb[4];
            #pragma unroll
            for (int c = 0; c < 4; ++c) {
                int j = j0 + c;
                bb[c] = is_masked(i, j - i) ? 0.5f * (xi + st[0][j]) : 0.0f;
            }
            stcs4(bptr + q, bb[0], bb[1], bb[2], bb[3]);
        }

        // --- Build sparse max table levels 1..6 (no sync needed before this:
        // boundary pass only read st[0], and level-1 writers re-sync below). ---
        #pragma unroll
        for (int k = 1; k < 7; ++k) {
            __syncthreads();
            if (t < NN) {
                float v = st[k - 1][t];
                int o = t + (1 << (k - 1));
                if (o < NN) v = fmaxf(v, st[k - 1][o]);
                st[k][t] = v;
            }
        }
        __syncthreads();

        // --- Content tile: two-span sparse-table max query per masked cell. ---
        #pragma unroll
        for (int it = 0; it < 4; ++it) {
            int q  = t + it * 256;
            int i  = q >> 4;
            int j0 = (q & 15) << 2;
            float cc[4];
            #pragma unroll
            for (int c = 0; c < 4; ++c) {
                int j = j0 + c;
                int off = j - i;
                float m = 0.0f;
                if (is_masked(i, off)) {
                    int len = off + 1;
                    int k = 31 - __clz(len);          // floor(log2(len))
                    m = fmaxf(st[k][i], st[k][j + 1 - (1 << k)]);
                }
                cc[c] = m;
            }
            stcs4(cptr + q, cc[0], cc[1], cc[2], cc[3]);
        }
    } else {
        // Mask blocks: static 0/1 pattern, one block per mask batch slice.
        int mb = blk - BD;
        if (mb >= nMaskB) return;
        float4* mptr = reinterpret_cast<float4*>(out) + (size_t)BD * 2048 + (size_t)mb * 1024;
        #pragma unroll
        for (int it = 0; it < 4; ++it) {
            int q  = t + it * 256;
            int i  = q >> 4;
            int j0 = (q & 15) << 2;
            float mm[4];
            #pragma unroll
            for (int c = 0; c < 4; ++c) {
                mm[c] = is_masked(i, j0 + c - i) ? 1.0f : 0.0f;
            }
            stcs4(mptr + q, mm[0], mm[1], mm[2], mm[3]);
        }
    }
}

extern "C" void kernel_launch(void* const* d_in, const int* in_sizes, int n_in,
                              void* d_out, int out_size) {
    const float* x = (const float*)d_in[0];
    float* out = (float*)d_out;

    int BD = in_sizes[0] / NN;                 // B*D rows of x (8192)
    long long mapElems = 2LL * BD * NN * NN;   // boundary + content
    long long maskElems = (long long)out_size - mapElems;
    int nMaskB = maskElems > 0 ? (int)(maskElems / (NN * NN)) : 0;

    int grid = BD + nMaskB;
    sbc_kernel<<<grid, 256>>>(x, out, BD, nMaskB);
}

// round 8
// speedup vs baseline: 2.0703x; 2.0703x over previous
#include <cuda_runtime.h>
#include <cuda_bf16.h>

// SparseBoundaryContent: B=16, D=512, N=64.
// Closed form: masked (i,j): boundary = 0.5*(x[i]+x[j]), content = max(x[i..j]);
// diag = x[i]; else 0. Mask static. Output = [boundary | content | mask] f32.

#define NN 64
#define RPB 8           // rows of x per block
#define LVLS 7

__device__ __forceinline__ bool is_masked(int i, int off) {
    if (off < 0) return false;
    if (off <= 15) return true;                               // offs 0..15, all i
    if (off <= 31) return (off & 1) && ((i & 1) == 0);        // 17,19,..,31; i even
    if (off >= 35) return ((off & 3) == 3) && ((i & 3) == 0); // 35,39,..,63; i%4==0
    return false;
}

__global__ void __launch_bounds__(256)
sbc_kernel(const float* __restrict__ x, float* __restrict__ out,
           int BD, int nRowBlks, int nMaskB) {
    const int blk = blockIdx.x;
    const int t = threadIdx.x;

    if (blk < nRowBlks) {
        // st[k][r][p], flat: k*512 + r*64 + p
        __shared__ float st[LVLS * RPB * NN];
        const int r0 = blk * RPB;
        const int nR = min(RPB, BD - r0);

        // Load nR rows (nR*16 float4s) into level 0.
        for (int f = t; f < nR * (NN / 4); f += 256) {
            reinterpret_cast<float4*>(st)[f] =
                reinterpret_cast<const float4*>(x + (size_t)r0 * NN)[f];
        }
        __syncthreads();

        // Build sparse max table levels 1..6 for all rows (512 items/level).
        #pragma unroll
        for (int k = 1; k < LVLS; ++k) {
            const int bp = (k - 1) * (RPB * NN);
            const int bc = k * (RPB * NN);
            const int half = 1 << (k - 1);
            #pragma unroll
            for (int s = 0; s < 2; ++s) {
                int item = t + s * 256;
                int p = item & (NN - 1);
                float v = st[bp + item];
                if (p + half < NN) v = fmaxf(v, st[bp + item + half]);
                st[bc + item] = v;
            }
            __syncthreads();
        }

        float4* bout = reinterpret_cast<float4*>(out) + (size_t)r0 * 1024;
        float4* cout = reinterpret_cast<float4*>(out) + (size_t)BD * 1024 + (size_t)r0 * 1024;

        #pragma unroll
        for (int it = 0; it < 4; ++it) {
            const int q  = t + it * 256;
            const int i  = q >> 4;
            const int j0 = (q & 15) << 2;

            // Per-cell descriptors: computed ONCE, reused for all rows.
            unsigned mbits = 0;
            int aoff[4], boff[4];
            #pragma unroll
            for (int c = 0; c < 4; ++c) {
                int j = j0 + c;
                int off = j - i;
                if (is_masked(i, off)) mbits |= (1u << c);
                int len = off + 1;
                if (len < 1) len = 1;                 // unmasked cells: safe dummy
                int k = 31 - __clz(len);              // floor(log2(len))
                aoff[c] = k * (RPB * NN) + i;
                boff[c] = k * (RPB * NN) + j + 1 - (1 << k);
            }

            #pragma unroll
            for (int r = 0; r < RPB; ++r) {
                if (r >= nR) break;
                const int rb = r * NN;
                float xi = st[rb + i];
                float4 xj = *reinterpret_cast<const float4*>(&st[rb + j0]);
                float4 bb, cc;
                bb.x = (mbits & 1u) ? 0.5f * (xi + xj.x) : 0.0f;
                bb.y = (mbits & 2u) ? 0.5f * (xi + xj.y) : 0.0f;
                bb.z = (mbits & 4u) ? 0.5f * (xi + xj.z) : 0.0f;
                bb.w = (mbits & 8u) ? 0.5f * (xi + xj.w) : 0.0f;
                cc.x = (mbits & 1u) ? fmaxf(st[aoff[0] + rb], st[boff[0] + rb]) : 0.0f;
                cc.y = (mbits & 2u) ? fmaxf(st[aoff[1] + rb], st[boff[1] + rb]) : 0.0f;
                cc.z = (mbits & 4u) ? fmaxf(st[aoff[2] + rb], st[boff[2] + rb]) : 0.0f;
                cc.w = (mbits & 8u) ? fmaxf(st[aoff[3] + rb], st[boff[3] + rb]) : 0.0f;
                __stcs(&bout[(size_t)r * 1024 + q], bb);
                __stcs(&cout[(size_t)r * 1024 + q], cc);
            }
        }
    } else {
        // Mask blocks: static 0/1 pattern, one block per mask batch slice.
        int mb = blk - nRowBlks;
        if (mb >= nMaskB) return;
        float4* mptr = reinterpret_cast<float4*>(out) + (size_t)BD * 2048 + (size_t)mb * 1024;
        #pragma unroll
        for (int itm = 0; itm < 4; ++itm) {
            int q  = t + itm * 256;
            int i  = q >> 4;
            int j0 = (q & 15) << 2;
            float4 mm;
            mm.x = is_masked(i, j0 + 0 - i) ? 1.0f : 0.0f;
            mm.y = is_masked(i, j0 + 1 - i) ? 1.0f : 0.0f;
            mm.z = is_masked(i, j0 + 2 - i) ? 1.0f : 0.0f;
            mm.w = is_masked(i, j0 + 3 - i) ? 1.0f : 0.0f;
            __stcs(&mptr[q], mm);
        }
    }
}

extern "C" void kernel_launch(void* const* d_in, const int* in_sizes, int n_in,
                              void* d_out, int out_size) {
    const float* x = (const float*)d_in[0];
    float* out = (float*)d_out;

    int BD = in_sizes[0] / NN;                 // B*D rows of x (8192)
    long long mapElems = 2LL * BD * NN * NN;   // boundary + content
    long long maskElems = (long long)out_size - mapElems;
    int nMaskB = maskElems > 0 ? (int)(maskElems / (NN * NN)) : 0;

    int nRowBlks = (BD + RPB - 1) / RPB;
    int grid = nRowBlks + nMaskB;
    sbc_kernel<<<grid, 256>>>(x, out, BD, nRowBlks, nMaskB);
}